// round 10
// baseline (speedup 1.0000x reference)
#include <cuda_runtime.h>
#include <cuda_bf16.h>
#include <math.h>
#include <stdint.h>

// Problem constants
#define B_   8
#define MB_  512
#define IN_  1024
#define EMB_ 1024
#define H_   16
#define KVH_ 4
#define HD_  64
#define BS_  16
#define KW_  32
#define NJ_  288
#define NJP  288
#define MTOT (B_*MB_)      // 4096
#define GRID 148
#define NTHR 512

// 1/sqrt(64) * log2(e): scores in log2 domain -> exp2 in P2 epilogue
#define SCORE_SCALE 0.1803368801111204f

typedef unsigned long long ull;

// Device scratch
__device__ float g_qT[HD_*256 + 64];             // [d][j = h*16+q]
__device__ float g_WoR[EMB_*2 + 64];             // [f][c]
__device__ __nv_bfloat16 g_Ahi[MTOT*IN_];        // h hi (bf16)
__device__ __nv_bfloat16 g_Alo[MTOT*IN_];        // h residual (bf16)
__device__ __nv_bfloat16 g_Bhi[NJ_*IN_];         // WcombT hi
__device__ __nv_bfloat16 g_Blo[NJ_*IN_];         // WcombT lo
__device__ float g_P[MTOT*NJP + 64];             // [m][j]; score cols exp'd

// grid barrier state
__device__ unsigned g_bar_ctr  = 0;
__device__ unsigned g_bar_sense = 0;

// ---------------------------------------------------------------------------
__device__ __forceinline__ uint32_t smem_u32(const void* p) {
    uint32_t a;
    asm("{ .reg .u64 t; cvta.to.shared.u64 t, %1; cvt.u32.u64 %0, t; }"
        : "=r"(a) : "l"(p));
    return a;
}
__device__ __forceinline__ unsigned ld_acq(const unsigned* p) {
    unsigned v;
    asm volatile("ld.acquire.gpu.u32 %0, [%1];" : "=r"(v) : "l"(p) : "memory");
    return v;
}
__device__ __forceinline__ void ldsm4(uint32_t* r, uint32_t a) {
    asm volatile("ldmatrix.sync.aligned.m8n8.x4.shared.b16 {%0,%1,%2,%3}, [%4];"
                 : "=r"(r[0]), "=r"(r[1]), "=r"(r[2]), "=r"(r[3]) : "r"(a));
}
__device__ __forceinline__ void mma4(float* d, const uint32_t* a,
                                     uint32_t b0, uint32_t b1) {
    asm volatile(
        "mma.sync.aligned.m16n8k16.row.col.f32.bf16.bf16.f32 "
        "{%0,%1,%2,%3}, {%4,%5,%6,%7}, {%8,%9}, {%0,%1,%2,%3};"
        : "+f"(d[0]), "+f"(d[1]), "+f"(d[2]), "+f"(d[3])
        : "r"(a[0]), "r"(a[1]), "r"(a[2]), "r"(a[3]), "r"(b0), "r"(b1));
}
__device__ __forceinline__ void cpa16(uint32_t smem, const void* g) {
    asm volatile("cp.async.cg.shared.global [%0], [%1], 16;"
                 :: "r"(smem), "l"(g) : "memory");
}
__device__ __forceinline__ void cpa_commit() {
    asm volatile("cp.async.commit_group;" ::: "memory");
}
template <int N> __device__ __forceinline__ void cpa_wait() {
    asm volatile("cp.async.wait_group %0;" :: "n"(N) : "memory");
}
// polynomial exp2 (FMA pipe, ~2e-7 rel) — avoids MUFU serialization
__device__ __forceinline__ float exp2poly(float x) {
    float xf = floorf(x);
    float f  = x - xf;
    float p  = 1.535336188319500e-4f;
    p = fmaf(p, f, 1.339887440266574e-3f);
    p = fmaf(p, f, 9.618437357674640e-3f);
    p = fmaf(p, f, 5.550332471162809e-2f);
    p = fmaf(p, f, 2.402264791363012e-1f);
    p = fmaf(p, f, 6.931472028550421e-1f);
    p = fmaf(p, f, 1.0f);
    int ei = (int)xf;
    return p * __int_as_float((ei + 127) << 23);
}
// fast reciprocal (FMA pipe, 3 Newton steps, ~1e-6 rel; x > 0 normal)
__device__ __forceinline__ float rcp_fast(float x) {
    float r = __int_as_float(0x7EF477D5u - __float_as_uint(x));
    r = r * (2.0f - x*r);
    r = r * (2.0f - x*r);
    r = r * (2.0f - x*r);
    return r;
}
// 8 fp32 -> bf16 hi (rn) + bf16 lo (residual), packed 16B each
__device__ __forceinline__ void cvt8(float4 f0, float4 f1, uint4& hi, uint4& lo) {
    float a[8] = {f0.x, f0.y, f0.z, f0.w, f1.x, f1.y, f1.z, f1.w};
    uint32_t h[4], l[4];
    #pragma unroll
    for (int i = 0; i < 4; i++) {
        float x = a[2*i], y = a[2*i+1];
        __nv_bfloat162 hb = __floats2bfloat162_rn(x, y);
        float hx = __bfloat162float(__low2bfloat16(hb));
        float hy = __bfloat162float(__high2bfloat16(hb));
        __nv_bfloat162 lb = __floats2bfloat162_rn(x - hx, y - hy);
        h[i] = *reinterpret_cast<uint32_t*>(&hb);
        l[i] = *reinterpret_cast<uint32_t*>(&lb);
    }
    hi = make_uint4(h[0], h[1], h[2], h[3]);
    lo = make_uint4(l[0], l[1], l[2], l[3]);
}

// ---------------------------------------------------------------------------
// P2 SMEM buffer layout (bf16, row stride 144B, K-chunk 64):
#define P2STR 144
#define P2AL  18432
#define P2BH  36864
#define P2BL  46080
#define P2BUF 55296
#define SMEM_BYTES (2*P2BUF)     // 110592

// P3
#define MT 32
#define ROWS (MT + KW_ - 1)   // 63
#define SSTR 272

extern __shared__ char dynsm[];

__global__ __launch_bounds__(NTHR, 1)
void mega(const float* __restrict__ hA,   // (8,512,1024)
          const float* __restrict__ fc,   // (512,64)
          const float* __restrict__ fs,   // (512,64)
          const float* __restrict__ Wq,   // (1024,1024)
          const float* __restrict__ Wk,   // (1024,256)
          const float* __restrict__ Wv,   // (1024,256)
          const float* __restrict__ Wo,   // (1024,1024)
          const float* __restrict__ oq,   // (16,1024)
          const float* __restrict__ Wr,   // (1024,2)
          const float* __restrict__ br,   // (2,)
          float* __restrict__ out)
{
    __shared__ unsigned s_sense;
    const int tid = threadIdx.x;
    const int bid = blockIdx.x;
    const int wid = tid >> 5;
    const int lane = tid & 31;

    if (tid == 0) s_sense = ld_acq(&g_bar_sense);

    auto gbar = [&]() {
        __syncthreads();
        if (tid == 0) {
            __threadfence();
            unsigned old = atomicInc(&g_bar_ctr, GRID - 1u);
            if (old == GRID - 1u) {
                atomicAdd(&g_bar_sense, 1u);
            } else {
                unsigned spins = 0;
                while (ld_acq(&g_bar_sense) == s_sense) {
                    if (++spins > 200000000u) break;
                }
            }
            s_sense++;
            __threadfence();
        }
        __syncthreads();
    };

    // =======================================================================
    // P0a: blocks [0,64): q = RoPE(oq @ Wq) -> g_qT (transposed)
    // P0b: blocks [64,148): WoR = Wo @ Wr, then hA -> bf16 hi/lo conversion
    //      (A conversion runs in the shadow of the longer q-projection)
    // =======================================================================
    if (bid < 64) {
        float* oqs  = (float*)dynsm;
        float* red  = oqs + 1024;
        float* rawS = red + 2048;
        const int qq = bid >> 2;
        const int cg = bid & 3;
        for (int i = tid; i < EMB_; i += NTHR) oqs[i] = oq[qq*EMB_ + i];
        __syncthreads();

        const int c4 = tid & 63;
        const int eh = tid >> 6;              // 0..7
        const int col0 = cg*256 + c4*4;
        const int e0 = eh*128;
        float4 acc4 = make_float4(0.f, 0.f, 0.f, 0.f);
        const float* wp = Wq + (size_t)e0 * EMB_ + col0;
        #pragma unroll 1
        for (int e = 0; e < 128; e += 16) {
            #pragma unroll
            for (int v = 0; v < 16; v++) {
                float4 w4 = *(const float4*)(wp + (size_t)(e+v)*EMB_);
                float ov = oqs[e0 + e + v];
                acc4.x += w4.x*ov; acc4.y += w4.y*ov;
                acc4.z += w4.z*ov; acc4.w += w4.w*ov;
            }
        }
        *(float4*)&red[eh*256 + c4*4] = acc4;
        __syncthreads();
        if (tid < 64) {
            #pragma unroll
            for (int i = 0; i < 4; i++) {
                int c = c4*4 + i;
                float s = 0.f;
                #pragma unroll
                for (int sl = 0; sl < 8; sl++) s += red[sl*256 + c];
                rawS[c] = s;
            }
        }
        __syncthreads();
        if (tid < 256) {
            int c   = tid;
            int col = cg*256 + c;
            int hh  = col >> 6;
            int d   = col & 63;
            int lp  = (c & ~63) | ((d < 32) ? d + 32 : d - 32);
            float rh = (d < 32) ? -rawS[lp] : rawS[lp];
            float val = rawS[c] * fc[qq*HD_ + d] + rh * fs[qq*HD_ + d];
            g_qT[d*256 + hh*BS_ + qq] = val;
        }
    } else {
        float* wrs = (float*)dynsm;
        for (int i = tid; i < 2048; i += NTHR) wrs[i] = Wr[i];
        __syncthreads();
        int r = (bid - 64)*16 + wid;          // 0..1343
        if (r < EMB_) {
            const float* wor = Wo + (size_t)r * EMB_;
            float p0 = 0.f, p1 = 0.f;
            #pragma unroll 4
            for (int i = 0; i < 32; i++) {
                int f = i*32 + lane;
                float wv = wor[f];
                p0 += wv * wrs[f*2 + 0];
                p1 += wv * wrs[f*2 + 1];
            }
            #pragma unroll
            for (int off = 16; off > 0; off >>= 1) {
                p0 += __shfl_xor_sync(0xffffffff, p0, off);
                p1 += __shfl_xor_sync(0xffffffff, p1, off);
            }
            if (lane == 0) { g_WoR[r*2+0] = p0; g_WoR[r*2+1] = p1; }
        }
        // A conversion: hA fp32 -> g_Ahi/g_Alo bf16 (84 blocks)
        const int nth = 84 * NTHR;
        int gt = (bid - 64)*NTHR + tid;
        for (size_t g = gt; g < (size_t)MTOT*IN_/8; g += nth) {
            const float* src = hA + g*8;
            float4 f0 = *(const float4*)src;
            float4 f1 = *(const float4*)(src + 4);
            uint4 hi4, lo4;
            cvt8(f0, f1, hi4, lo4);
            *(uint4*)((char*)g_Ahi + g*16) = hi4;
            *(uint4*)((char*)g_Alo + g*16) = lo4;
        }
    }
    gbar();

    // =======================================================================
    // P1: blocks [0,64): WcombT as bf16 hi/lo -> g_Bhi/g_Blo (16 e each)
    // =======================================================================
    if (bid < 64) {
        float* wks  = (float*)dynsm;
        float* wvs  = wks + 16*256;
        float* WoRs = wvs + 16*256;
        const int e0 = bid * 16;
        for (int idx = tid; idx < 4096; idx += NTHR) {
            int e = idx >> 8, jj = idx & 255;
            wks[idx] = Wk[(size_t)(e0+e)*256 + jj];
            wvs[idx] = Wv[(size_t)(e0+e)*256 + jj];
        }
        for (int idx = tid; idx < 2048; idx += NTHR) {
            int f = idx >> 1, c = idx & 1;
            int hh = f >> 6, d = f & 63;
            WoRs[hh*130 + d*2 + c] = g_WoR[idx];
        }
        __syncthreads();

        float s[16];
        int jrow = -1;
        if (tid < 256) {
            int j  = tid;
            int hh = j >> 4;
            int kv = hh >> 2;
            #pragma unroll
            for (int e = 0; e < 16; e++) s[e] = 0.f;
            const float* qcol = g_qT + j;
            #pragma unroll 2
            for (int d = 0; d < HD_; d++) {
                float qd = qcol[d*256];
                #pragma unroll
                for (int e = 0; e < 16; e++)
                    s[e] += wks[e*256 + kv*HD_ + d] * qd;
            }
            #pragma unroll
            for (int e = 0; e < 16; e++) s[e] *= SCORE_SCALE;
            jrow = j;
        } else if (tid < 288) {
            int j2 = tid - 256;
            int hh = j2 >> 1;
            int c  = j2 & 1;
            int kv = hh >> 2;
            #pragma unroll
            for (int e = 0; e < 16; e++) s[e] = 0.f;
            #pragma unroll 2
            for (int d = 0; d < HD_; d++) {
                float wv = WoRs[hh*130 + d*2 + c];
                #pragma unroll
                for (int e = 0; e < 16; e++)
                    s[e] += wvs[e*256 + kv*HD_ + d] * wv;
            }
            jrow = 256 + j2;
        }
        if (jrow >= 0) {
            #pragma unroll
            for (int e = 0; e < 16; e++) {
                __nv_bfloat16 hb = __float2bfloat16(s[e]);
                __nv_bfloat16 lb = __float2bfloat16(s[e] - __bfloat162float(hb));
                g_Bhi[(size_t)jrow * IN_ + e0 + e] = hb;
                g_Blo[(size_t)jrow * IN_ + e0 + e] = lb;
            }
        }
    }
    gbar();

    // =======================================================================
    // P2: HMMA GEMM P[4096,288] = A @ B^T, bf16 hi/lo split (3 products).
    // Tiles: 128 full (M=128,N=64) + 32 half (M=128,N=32, value cols).
    // MMA order: round-robin over 4 accumulators per product group (gap 4).
    // =======================================================================
    {
        const uint32_t sbase = smem_u32(dynsm);

        int ntask = 0;
        int t_m0[2], t_n0[2], t_nb[2];
        if (bid < 12) {
            ntask = 2;
            t_m0[0] = (2*bid)   * 128; t_n0[0] = 256; t_nb[0] = 32;
            t_m0[1] = (2*bid+1) * 128; t_n0[1] = 256; t_nb[1] = 32;
        } else if (bid < 20) {
            ntask = 1;
            t_m0[0] = (24 + bid - 12) * 128; t_n0[0] = 256; t_nb[0] = 32;
        } else {
            ntask = 1;
            int f = bid - 20;               // 0..127
            t_m0[0] = (f & 31) * 128; t_n0[0] = (f >> 5) * 64; t_nb[0] = 64;
        }

        for (int ti = 0; ti < ntask; ti++) {
            const int m0 = t_m0[ti], n0 = t_n0[ti], nb = t_nb[ti];

            auto stage = [&](int c) {
                uint32_t dst = sbase + (c & 1)*P2BUF;
                int k0 = c * 64;
                #pragma unroll
                for (int i = 0; i < 2; i++) {
                    int g = tid + i*512;
                    int row = g >> 3, kg = g & 7;
                    size_t so = (size_t)(m0 + row)*IN_ + k0 + kg*8;
                    cpa16(dst + row*P2STR + kg*16,        g_Ahi + so);
                    cpa16(dst + P2AL + row*P2STR + kg*16, g_Alo + so);
                }
                if (tid < nb*8) {
                    int row = tid >> 3, kg = tid & 7;
                    size_t so = (size_t)(n0 + row)*IN_ + k0 + kg*8;
                    cpa16(dst + P2BH + row*P2STR + kg*16, g_Bhi + so);
                    cpa16(dst + P2BL + row*P2STR + kg*16, g_Blo + so);
                }
                cpa_commit();
            };

            if (nb == 64) {
                const int wm = (wid & 3) * 32;
                const int wn = (wid >> 2) * 16;
                const uint32_t aof = (wm + (lane & 15))*P2STR + (lane >> 4)*16;
                const uint32_t bof = (wn + (lane & 15))*P2STR + (lane >> 4)*16;
                float acc[2][2][4];
                #pragma unroll
                for (int i = 0; i < 2; i++)
                    #pragma unroll
                    for (int j = 0; j < 2; j++)
                        #pragma unroll
                        for (int k = 0; k < 4; k++) acc[i][j][k] = 0.f;

                stage(0);
                for (int c = 0; c < 16; c++) {
                    if (c < 15) { stage(c + 1); cpa_wait<1>(); }
                    else        { cpa_wait<0>(); }
                    __syncthreads();
                    uint32_t bb = sbase + (c & 1)*P2BUF;
                    #pragma unroll
                    for (int ks = 0; ks < 4; ks++) {
                        uint32_t ko = ks*32;
                        uint32_t ah0[4], ah1[4], al0[4], al1[4], bh[4], bl[4];
                        ldsm4(ah0, bb + aof + ko);
                        ldsm4(ah1, bb + aof + 16*P2STR + ko);
                        ldsm4(al0, bb + P2AL + aof + ko);
                        ldsm4(al1, bb + P2AL + aof + 16*P2STR + ko);
                        ldsm4(bh,  bb + P2BH + bof + ko);
                        ldsm4(bl,  bb + P2BL + bof + ko);
                        // round-robin accumulators: dependent gap = 4
                        mma4(acc[0][0], ah0, bh[0], bh[2]);
                        mma4(acc[0][1], ah0, bh[1], bh[3]);
                        mma4(acc[1][0], ah1, bh[0], bh[2]);
                        mma4(acc[1][1], ah1, bh[1], bh[3]);
                        mma4(acc[0][0], ah0, bl[0], bl[2]);
                        mma4(acc[0][1], ah0, bl[1], bl[3]);
                        mma4(acc[1][0], ah1, bl[0], bl[2]);
                        mma4(acc[1][1], ah1, bl[1], bl[3]);
                        mma4(acc[0][0], al0, bh[0], bh[2]);
                        mma4(acc[0][1], al0, bh[1], bh[3]);
                        mma4(acc[1][0], al1, bh[0], bh[2]);
                        mma4(acc[1][1], al1, bh[1], bh[3]);
                    }
                    __syncthreads();
                }
                #pragma unroll
                for (int tm = 0; tm < 2; tm++) {
                    #pragma unroll
                    for (int tn = 0; tn < 2; tn++) {
                        int row = m0 + wm + tm*16 + (lane >> 2);
                        int col = n0 + wn + tn*8 + (lane & 3)*2;
                        float* d0 = g_P + (size_t)row*NJP + col;
                        float* d1 = g_P + (size_t)(row+8)*NJP + col;
                        *(float2*)d0 = make_float2(exp2poly(acc[tm][tn][0]),
                                                   exp2poly(acc[tm][tn][1]));
                        *(float2*)d1 = make_float2(exp2poly(acc[tm][tn][2]),
                                                   exp2poly(acc[tm][tn][3]));
                    }
                }
            } else {
                const int wm = (wid & 7) * 16;
                const int wn = (wid >> 3) * 16;
                const uint32_t aof = (wm + (lane & 15))*P2STR + (lane >> 4)*16;
                const uint32_t bof = (wn + (lane & 15))*P2STR + (lane >> 4)*16;
                float acc[2][4];
                #pragma unroll
                for (int j = 0; j < 2; j++)
                    #pragma unroll
                    for (int k = 0; k < 4; k++) acc[j][k] = 0.f;

                stage(0);
                for (int c = 0; c < 16; c++) {
                    if (c < 15) { stage(c + 1); cpa_wait<1>(); }
                    else        { cpa_wait<0>(); }
                    __syncthreads();
                    uint32_t bb = sbase + (c & 1)*P2BUF;
                    #pragma unroll
                    for (int ks = 0; ks < 4; ks++) {
                        uint32_t ko = ks*32;
                        uint32_t ah[4], al[4], bh[4], bl[4];
                        ldsm4(ah, bb + aof + ko);
                        ldsm4(al, bb + P2AL + aof + ko);
                        ldsm4(bh, bb + P2BH + bof + ko);
                        ldsm4(bl, bb + P2BL + bof + ko);
                        mma4(acc[0], ah, bh[0], bh[2]);
                        mma4(acc[1], ah, bh[1], bh[3]);
                        mma4(acc[0], ah, bl[0], bl[2]);
                        mma4(acc[1], ah, bl[1], bl[3]);
                        mma4(acc[0], al, bh[0], bh[2]);
                        mma4(acc[1], al, bh[1], bh[3]);
                    }
                    __syncthreads();
                }
                #pragma unroll
                for (int tn = 0; tn < 2; tn++) {
                    int row = m0 + wm + (lane >> 2);
                    int col = n0 + wn + tn*8 + (lane & 3)*2;
                    *(float2*)(g_P + (size_t)row*NJP + col) =
                        make_float2(acc[tn][0], acc[tn][1]);
                    *(float2*)(g_P + (size_t)(row+8)*NJP + col) =
                        make_float2(acc[tn][2], acc[tn][3]);
                }
            }
        }
    }
    gbar();

    // =======================================================================
    // P3: windowed attention (P already exp'd) + 2-col output.
    // MT=32 -> 128 tiles = one wave.
    // =======================================================================
    {
        float* Es  = (float*)dynsm;            // 63*272
        float* Pvs = Es + ROWS*SSTR;           // 63*32
        const float br0 = br[0], br1 = br[1];
        const int q  = tid & 15;
        const int ml = tid >> 4;               // 0..31

        for (int t = bid; t < 128; t += GRID) {
            int b  = t >> 4;
            int m0 = (t & 15) * MT;
            __syncthreads();

            for (int g = tid; g < ROWS*72; g += NTHR) {
                int r  = g / 72;
                int c4 = g - r*72;
                int grow = m0 - (KW_-1) + r;
                float4 v;
                if (grow >= 0)
                    v = *(const float4*)(g_P + ((size_t)(b*MB_ + grow))*NJP + c4*4);
                else
                    v = (c4 < 64) ? make_float4(1.f,1.f,1.f,1.f)
                                  : make_float4(0.f,0.f,0.f,0.f);
                if (c4 < 64) *(float4*)&Es[r*SSTR + c4*4] = v;
                else         *(float4*)&Pvs[r*32 + (c4-64)*4] = v;
            }
            __syncthreads();

            float o0 = 0.f, o1 = 0.f;
            #pragma unroll 1
            for (int hh = 0; hh < H_; hh++) {
                int col = hh*16 + q;
                float sum = 0.f, a0 = 0.f, a1 = 0.f;
                #pragma unroll
                for (int k = 0; k < KW_; k++) {
                    float w = Es[(ml + k)*SSTR + col];
                    float2 pv = *(const float2*)&Pvs[(ml + k)*32 + 2*hh];
                    sum += w;
                    a0 += w * pv.x;
                    a1 += w * pv.y;
                }
                float inv = rcp_fast(sum);
                o0 += a0 * inv;
                o1 += a1 * inv;
            }
            int m = m0 + ml;
            size_t o = (((size_t)(b*MB_ + m))*BS_ + q);
            *(float2*)(out + o*2) = make_float2(o0 + br0, o1 + br1);
        }
    }
}

// ---------------------------------------------------------------------------
extern "C" void kernel_launch(void* const* d_in, const int* in_sizes, int n_in,
                              void* d_out, int out_size)
{
    const float* h   = (const float*)d_in[0];
    const float* fc  = (const float*)d_in[1];
    const float* fs  = (const float*)d_in[2];
    const float* Wq  = (const float*)d_in[3];
    const float* Wk  = (const float*)d_in[4];
    const float* Wv  = (const float*)d_in[5];
    const float* Wo  = (const float*)d_in[6];
    const float* oq  = (const float*)d_in[7];
    const float* Wr  = (const float*)d_in[8];
    const float* br  = (const float*)d_in[9];
    float* out = (float*)d_out;

    cudaFuncSetAttribute(mega, cudaFuncAttributeMaxDynamicSharedMemorySize,
                         SMEM_BYTES);
    mega<<<GRID, NTHR, SMEM_BYTES>>>(h, fc, fs, Wq, Wk, Wv, Wo, oq, Wr, br, out);
}

// round 11
// speedup vs baseline: 1.0515x; 1.0515x over previous
#include <cuda_runtime.h>
#include <cuda_bf16.h>
#include <math.h>
#include <stdint.h>

// Problem constants
#define B_   8
#define MB_  512
#define IN_  1024
#define EMB_ 1024
#define H_   16
#define KVH_ 4
#define HD_  64
#define BS_  16
#define KW_  32
#define NJ_  288
#define NJP  288
#define MTOT (B_*MB_)      // 4096
#define GRID 296           // 2 persistent blocks per SM
#define NTHR 512

// 1/sqrt(64) * log2(e): scores in log2 domain -> exp2 in P2 epilogue
#define SCORE_SCALE 0.1803368801111204f

typedef unsigned long long ull;

// Device scratch
__device__ float g_qT[HD_*256 + 64];             // [d][j = h*16+q]
__device__ float g_WoR[EMB_*2 + 64];             // [f][c]
__device__ __nv_bfloat16 g_Ahi[MTOT*IN_];        // h hi (bf16)
__device__ __nv_bfloat16 g_Alo[MTOT*IN_];        // h residual (bf16)
__device__ __nv_bfloat16 g_Bhi[NJ_*IN_];         // WcombT hi
__device__ __nv_bfloat16 g_Blo[NJ_*IN_];         // WcombT lo
__device__ float g_P[MTOT*NJP + 64];             // [m][j]; score cols exp'd

// grid barrier state
__device__ unsigned g_bar_ctr  = 0;
__device__ unsigned g_bar_sense = 0;

// ---------------------------------------------------------------------------
__device__ __forceinline__ uint32_t smem_u32(const void* p) {
    uint32_t a;
    asm("{ .reg .u64 t; cvta.to.shared.u64 t, %1; cvt.u32.u64 %0, t; }"
        : "=r"(a) : "l"(p));
    return a;
}
__device__ __forceinline__ unsigned ld_acq(const unsigned* p) {
    unsigned v;
    asm volatile("ld.acquire.gpu.u32 %0, [%1];" : "=r"(v) : "l"(p) : "memory");
    return v;
}
__device__ __forceinline__ void ldsm4(uint32_t* r, uint32_t a) {
    asm volatile("ldmatrix.sync.aligned.m8n8.x4.shared.b16 {%0,%1,%2,%3}, [%4];"
                 : "=r"(r[0]), "=r"(r[1]), "=r"(r[2]), "=r"(r[3]) : "r"(a));
}
__device__ __forceinline__ void mma4(float* d, const uint32_t* a,
                                     uint32_t b0, uint32_t b1) {
    asm volatile(
        "mma.sync.aligned.m16n8k16.row.col.f32.bf16.bf16.f32 "
        "{%0,%1,%2,%3}, {%4,%5,%6,%7}, {%8,%9}, {%0,%1,%2,%3};"
        : "+f"(d[0]), "+f"(d[1]), "+f"(d[2]), "+f"(d[3])
        : "r"(a[0]), "r"(a[1]), "r"(a[2]), "r"(a[3]), "r"(b0), "r"(b1));
}
__device__ __forceinline__ void cpa16(uint32_t smem, const void* g) {
    asm volatile("cp.async.cg.shared.global [%0], [%1], 16;"
                 :: "r"(smem), "l"(g) : "memory");
}
__device__ __forceinline__ void cpa_commit() {
    asm volatile("cp.async.commit_group;" ::: "memory");
}
template <int N> __device__ __forceinline__ void cpa_wait() {
    asm volatile("cp.async.wait_group %0;" :: "n"(N) : "memory");
}
// polynomial exp2 (FMA pipe, ~2e-7 rel)
__device__ __forceinline__ float exp2poly(float x) {
    float xf = floorf(x);
    float f  = x - xf;
    float p  = 1.535336188319500e-4f;
    p = fmaf(p, f, 1.339887440266574e-3f);
    p = fmaf(p, f, 9.618437357674640e-3f);
    p = fmaf(p, f, 5.550332471162809e-2f);
    p = fmaf(p, f, 2.402264791363012e-1f);
    p = fmaf(p, f, 6.931472028550421e-1f);
    p = fmaf(p, f, 1.0f);
    int ei = (int)xf;
    return p * __int_as_float((ei + 127) << 23);
}
// fast reciprocal (FMA pipe, 3 Newton steps, ~1e-6 rel; x > 0 normal)
__device__ __forceinline__ float rcp_fast(float x) {
    float r = __int_as_float(0x7EF477D5u - __float_as_uint(x));
    r = r * (2.0f - x*r);
    r = r * (2.0f - x*r);
    r = r * (2.0f - x*r);
    return r;
}
// 8 fp32 -> bf16 hi (rn) + bf16 lo (residual), packed 16B each
__device__ __forceinline__ void cvt8(float4 f0, float4 f1, uint4& hi, uint4& lo) {
    float a[8] = {f0.x, f0.y, f0.z, f0.w, f1.x, f1.y, f1.z, f1.w};
    uint32_t h[4], l[4];
    #pragma unroll
    for (int i = 0; i < 4; i++) {
        float x = a[2*i], y = a[2*i+1];
        __nv_bfloat162 hb = __floats2bfloat162_rn(x, y);
        float hx = __bfloat162float(__low2bfloat16(hb));
        float hy = __bfloat162float(__high2bfloat16(hb));
        __nv_bfloat162 lb = __floats2bfloat162_rn(x - hx, y - hy);
        h[i] = *reinterpret_cast<uint32_t*>(&hb);
        l[i] = *reinterpret_cast<uint32_t*>(&lb);
    }
    hi = make_uint4(h[0], h[1], h[2], h[3]);
    lo = make_uint4(l[0], l[1], l[2], l[3]);
}

// ---------------------------------------------------------------------------
// P2 SMEM buffer (bf16, row stride 144B, K-chunk 64, tile M=128 N=32):
//  AH @0 (128x144=18432)  AL @18432  BH @36864 (32x144=4608)  BL @41472
#define P2STR 144
#define P2AL  18432
#define P2BH  36864
#define P2BL  41472
#define P2BUF 46080
#define SMEM_BYTES (2*P2BUF)     // 92160; x2 blocks = 184320 < 228KB

// P3
#define MT 16
#define ROWS (MT + KW_ - 1)   // 47
#define SSTR 272

extern __shared__ char dynsm[];

__global__ __launch_bounds__(NTHR, 2)
void mega(const float* __restrict__ hA,   // (8,512,1024)
          const float* __restrict__ fc,   // (512,64)
          const float* __restrict__ fs,   // (512,64)
          const float* __restrict__ Wq,   // (1024,1024)
          const float* __restrict__ Wk,   // (1024,256)
          const float* __restrict__ Wv,   // (1024,256)
          const float* __restrict__ Wo,   // (1024,1024)
          const float* __restrict__ oq,   // (16,1024)
          const float* __restrict__ Wr,   // (1024,2)
          const float* __restrict__ br,   // (2,)
          float* __restrict__ out)
{
    __shared__ unsigned s_sense;
    const int tid = threadIdx.x;
    const int bid = blockIdx.x;
    const int wid = tid >> 5;
    const int lane = tid & 31;

    if (tid == 0) s_sense = ld_acq(&g_bar_sense);

    auto gbar = [&]() {
        __syncthreads();
        if (tid == 0) {
            __threadfence();
            unsigned old = atomicInc(&g_bar_ctr, GRID - 1u);
            if (old == GRID - 1u) {
                atomicAdd(&g_bar_sense, 1u);
            } else {
                unsigned spins = 0;
                while (ld_acq(&g_bar_sense) == s_sense) {
                    if (++spins > 200000000u) break;
                }
            }
            s_sense++;
            __threadfence();
        }
        __syncthreads();
    };

    // =======================================================================
    // P0a: blocks [0,64): q = RoPE(oq @ Wq) -> g_qT (transposed)
    // P0b: blocks [64,296): WoR = Wo @ Wr (first 64 of them), then
    //      hA -> bf16 hi/lo conversion spread over all 232 blocks.
    // =======================================================================
    if (bid < 64) {
        float* oqs  = (float*)dynsm;
        float* red  = oqs + 1024;
        float* rawS = red + 2048;
        const int qq = bid >> 2;
        const int cg = bid & 3;
        for (int i = tid; i < EMB_; i += NTHR) oqs[i] = oq[qq*EMB_ + i];
        __syncthreads();

        const int c4 = tid & 63;
        const int eh = tid >> 6;              // 0..7
        const int col0 = cg*256 + c4*4;
        const int e0 = eh*128;
        float4 acc4 = make_float4(0.f, 0.f, 0.f, 0.f);
        const float* wp = Wq + (size_t)e0 * EMB_ + col0;
        #pragma unroll 1
        for (int e = 0; e < 128; e += 8) {
            #pragma unroll
            for (int v = 0; v < 8; v++) {
                float4 w4 = *(const float4*)(wp + (size_t)(e+v)*EMB_);
                float ov = oqs[e0 + e + v];
                acc4.x += w4.x*ov; acc4.y += w4.y*ov;
                acc4.z += w4.z*ov; acc4.w += w4.w*ov;
            }
        }
        *(float4*)&red[eh*256 + c4*4] = acc4;
        __syncthreads();
        if (tid < 64) {
            #pragma unroll
            for (int i = 0; i < 4; i++) {
                int c = c4*4 + i;
                float s = 0.f;
                #pragma unroll
                for (int sl = 0; sl < 8; sl++) s += red[sl*256 + c];
                rawS[c] = s;
            }
        }
        __syncthreads();
        if (tid < 256) {
            int c   = tid;
            int col = cg*256 + c;
            int hh  = col >> 6;
            int d   = col & 63;
            int lp  = (c & ~63) | ((d < 32) ? d + 32 : d - 32);
            float rh = (d < 32) ? -rawS[lp] : rawS[lp];
            float val = rawS[c] * fc[qq*HD_ + d] + rh * fs[qq*HD_ + d];
            g_qT[d*256 + hh*BS_ + qq] = val;
        }
    } else {
        float* wrs = (float*)dynsm;
        for (int i = tid; i < 2048; i += NTHR) wrs[i] = Wr[i];
        __syncthreads();
        int r = (bid - 64)*16 + wid;          // warps cover 0..3711
        if (r < EMB_) {
            const float* wor = Wo + (size_t)r * EMB_;
            float p0 = 0.f, p1 = 0.f;
            #pragma unroll 4
            for (int i = 0; i < 32; i++) {
                int f = i*32 + lane;
                float wv = wor[f];
                p0 += wv * wrs[f*2 + 0];
                p1 += wv * wrs[f*2 + 1];
            }
            #pragma unroll
            for (int off = 16; off > 0; off >>= 1) {
                p0 += __shfl_xor_sync(0xffffffff, p0, off);
                p1 += __shfl_xor_sync(0xffffffff, p1, off);
            }
            if (lane == 0) { g_WoR[r*2+0] = p0; g_WoR[r*2+1] = p1; }
        }
        // A conversion: hA fp32 -> g_Ahi/g_Alo bf16 (232 blocks)
        const int nth = (GRID - 64) * NTHR;
        int gt = (bid - 64)*NTHR + tid;
        for (size_t g = gt; g < (size_t)MTOT*IN_/8; g += nth) {
            const float* src = hA + g*8;
            float4 f0 = *(const float4*)src;
            float4 f1 = *(const float4*)(src + 4);
            uint4 hi4, lo4;
            cvt8(f0, f1, hi4, lo4);
            *(uint4*)((char*)g_Ahi + g*16) = hi4;
            *(uint4*)((char*)g_Alo + g*16) = lo4;
        }
    }
    gbar();

    // =======================================================================
    // P1: blocks [0,64): WcombT as bf16 hi/lo -> g_Bhi/g_Blo (16 e each)
    // =======================================================================
    if (bid < 64) {
        float* wks  = (float*)dynsm;
        float* wvs  = wks + 16*256;
        float* WoRs = wvs + 16*256;
        const int e0 = bid * 16;
        for (int idx = tid; idx < 4096; idx += NTHR) {
            int e = idx >> 8, jj = idx & 255;
            wks[idx] = Wk[(size_t)(e0+e)*256 + jj];
            wvs[idx] = Wv[(size_t)(e0+e)*256 + jj];
        }
        for (int idx = tid; idx < 2048; idx += NTHR) {
            int f = idx >> 1, c = idx & 1;
            int hh = f >> 6, d = f & 63;
            WoRs[hh*130 + d*2 + c] = g_WoR[idx];
        }
        __syncthreads();

        float s[16];
        int jrow = -1;
        if (tid < 256) {
            int j  = tid;
            int hh = j >> 4;
            int kv = hh >> 2;
            #pragma unroll
            for (int e = 0; e < 16; e++) s[e] = 0.f;
            const float* qcol = g_qT + j;
            #pragma unroll 2
            for (int d = 0; d < HD_; d++) {
                float qd = qcol[d*256];
                #pragma unroll
                for (int e = 0; e < 16; e++)
                    s[e] += wks[e*256 + kv*HD_ + d] * qd;
            }
            #pragma unroll
            for (int e = 0; e < 16; e++) s[e] *= SCORE_SCALE;
            jrow = j;
        } else if (tid < 288) {
            int j2 = tid - 256;
            int hh = j2 >> 1;
            int c  = j2 & 1;
            int kv = hh >> 2;
            #pragma unroll
            for (int e = 0; e < 16; e++) s[e] = 0.f;
            #pragma unroll 2
            for (int d = 0; d < HD_; d++) {
                float wv = WoRs[hh*130 + d*2 + c];
                #pragma unroll
                for (int e = 0; e < 16; e++)
                    s[e] += wvs[e*256 + kv*HD_ + d] * wv;
            }
            jrow = 256 + j2;
        }
        if (jrow >= 0) {
            #pragma unroll
            for (int e = 0; e < 16; e++) {
                __nv_bfloat16 hb = __float2bfloat16(s[e]);
                __nv_bfloat16 lb = __float2bfloat16(s[e] - __bfloat162float(hb));
                g_Bhi[(size_t)jrow * IN_ + e0 + e] = hb;
                g_Blo[(size_t)jrow * IN_ + e0 + e] = lb;
            }
        }
    }
    gbar();

    // =======================================================================
    // P2: HMMA GEMM P[4096,288] = A @ B^T, bf16 hi/lo split (3 products).
    // 288 tiles (M=128, N=32) over 296 blocks = one wave.
    // 16 warps = 8m x 2n, warp tile m16n16.
    // =======================================================================
    if (bid < 288) {
        const uint32_t sbase = smem_u32(dynsm);
        const int m0 = (bid & 31) * 128;
        const int n0 = (bid >> 5) * 32;
        const bool isScore = (n0 < 256);

        auto stage = [&](int c) {
            uint32_t dst = sbase + (c & 1)*P2BUF;
            int k0 = c * 64;
            #pragma unroll
            for (int i = 0; i < 2; i++) {
                int g = tid + i*512;
                int row = g >> 3, kg = g & 7;
                size_t so = (size_t)(m0 + row)*IN_ + k0 + kg*8;
                cpa16(dst + row*P2STR + kg*16,        g_Ahi + so);
                cpa16(dst + P2AL + row*P2STR + kg*16, g_Alo + so);
            }
            if (tid < 256) {
                int row = tid >> 3, kg = tid & 7;
                size_t so = (size_t)(n0 + row)*IN_ + k0 + kg*8;
                cpa16(dst + P2BH + row*P2STR + kg*16, g_Bhi + so);
                cpa16(dst + P2BL + row*P2STR + kg*16, g_Blo + so);
            }
            cpa_commit();
        };

        const int wm = (wid & 7) * 16;
        const int wn = (wid >> 3) * 16;
        const uint32_t aof = (wm + (lane & 15))*P2STR + (lane >> 4)*16;
        const uint32_t bof = (wn + (lane & 15))*P2STR + (lane >> 4)*16;
        float acc[2][4];
        #pragma unroll
        for (int j = 0; j < 2; j++)
            #pragma unroll
            for (int k = 0; k < 4; k++) acc[j][k] = 0.f;

        stage(0);
        for (int c = 0; c < 16; c++) {
            if (c < 15) { stage(c + 1); cpa_wait<1>(); }
            else        { cpa_wait<0>(); }
            __syncthreads();
            uint32_t bb = sbase + (c & 1)*P2BUF;
            #pragma unroll
            for (int ks = 0; ks < 4; ks++) {
                uint32_t ko = ks*32;
                uint32_t ah[4], al[4], bh[4], bl[4];
                ldsm4(ah, bb + aof + ko);
                ldsm4(al, bb + P2AL + aof + ko);
                ldsm4(bh, bb + P2BH + bof + ko);
                ldsm4(bl, bb + P2BL + bof + ko);
                mma4(acc[0], ah, bh[0], bh[2]);
                mma4(acc[1], ah, bh[1], bh[3]);
                mma4(acc[0], ah, bl[0], bl[2]);
                mma4(acc[1], ah, bl[1], bl[3]);
                mma4(acc[0], al, bh[0], bh[2]);
                mma4(acc[1], al, bh[1], bh[3]);
            }
            __syncthreads();
        }
        #pragma unroll
        for (int tn = 0; tn < 2; tn++) {
            int row = m0 + wm + (lane >> 2);
            int col = n0 + wn + tn*8 + (lane & 3)*2;
            float* d0 = g_P + (size_t)row*NJP + col;
            float* d1 = g_P + (size_t)(row+8)*NJP + col;
            if (isScore) {
                *(float2*)d0 = make_float2(exp2poly(acc[tn][0]),
                                           exp2poly(acc[tn][1]));
                *(float2*)d1 = make_float2(exp2poly(acc[tn][2]),
                                           exp2poly(acc[tn][3]));
            } else {
                *(float2*)d0 = make_float2(acc[tn][0], acc[tn][1]);
                *(float2*)d1 = make_float2(acc[tn][2], acc[tn][3]);
            }
        }
    }
    gbar();

    // =======================================================================
    // P3: windowed attention (P already exp'd) + 2-col output.
    // MT=16 -> 256 tiles over 296 blocks. 512 threads =
    // (hg 0..1) x (ml 0..15) x (q 0..15); hg splits 16 heads in two.
    // =======================================================================
    if (bid < 256) {
        float* Es  = (float*)dynsm;            // 47*272
        float* Pvs = Es + ROWS*SSTR;           // 47*32
        const float br0 = br[0], br1 = br[1];
        const int q  = tid & 15;
        const int ml = (tid >> 4) & 15;
        const int hg = tid >> 8;               // 0..1

        const int t  = bid;
        const int b  = t >> 5;
        const int m0 = (t & 31) * MT;

        for (int g = tid; g < ROWS*72; g += NTHR) {
            int r  = g / 72;
            int c4 = g - r*72;
            int grow = m0 - (KW_-1) + r;
            float4 v;
            if (grow >= 0)
                v = *(const float4*)(g_P + ((size_t)(b*MB_ + grow))*NJP + c4*4);
            else
                v = (c4 < 64) ? make_float4(1.f,1.f,1.f,1.f)
                              : make_float4(0.f,0.f,0.f,0.f);
            if (c4 < 64) *(float4*)&Es[r*SSTR + c4*4] = v;
            else         *(float4*)&Pvs[r*32 + (c4-64)*4] = v;
        }
        __syncthreads();

        float o0 = 0.f, o1 = 0.f;
        #pragma unroll 1
        for (int hi = 0; hi < 8; hi++) {
            int hh  = hg*8 + hi;
            int col = hh*16 + q;
            float sum = 0.f, a0 = 0.f, a1 = 0.f;
            #pragma unroll
            for (int k = 0; k < KW_; k++) {
                float w = Es[(ml + k)*SSTR + col];
                float2 pv = *(const float2*)&Pvs[(ml + k)*32 + 2*hh];
                sum += w;
                a0 += w * pv.x;
                a1 += w * pv.y;
            }
            float inv = rcp_fast(sum);
            o0 += a0 * inv;
            o1 += a1 * inv;
        }
        __syncthreads();
        float2* redv = (float2*)Es;
        redv[tid] = make_float2(o0, o1);
        __syncthreads();
        if (hg == 0) {
            float2 r0 = redv[tid];
            float2 r1 = redv[tid + 256];
            int m = m0 + ml;
            size_t o = (((size_t)(b*MB_ + m))*BS_ + q);
            *(float2*)(out + o*2) =
                make_float2(r0.x + r1.x + br0, r0.y + r1.y + br1);
        }
    }
}

// ---------------------------------------------------------------------------
extern "C" void kernel_launch(void* const* d_in, const int* in_sizes, int n_in,
                              void* d_out, int out_size)
{
    const float* h   = (const float*)d_in[0];
    const float* fc  = (const float*)d_in[1];
    const float* fs  = (const float*)d_in[2];
    const float* Wq  = (const float*)d_in[3];
    const float* Wk  = (const float*)d_in[4];
    const float* Wv  = (const float*)d_in[5];
    const float* Wo  = (const float*)d_in[6];
    const float* oq  = (const float*)d_in[7];
    const float* Wr  = (const float*)d_in[8];
    const float* br  = (const float*)d_in[9];
    float* out = (float*)d_out;

    cudaFuncSetAttribute(mega, cudaFuncAttributeMaxDynamicSharedMemorySize,
                         SMEM_BYTES);
    mega<<<GRID, NTHR, SMEM_BYTES>>>(h, fc, fs, Wq, Wk, Wv, Wo, oq, Wr, br, out);
}